// round 9
// baseline (speedup 1.0000x reference)
#include <cuda_runtime.h>
#include <cuda_fp16.h>
#include <cstdint>

// GIN (N=8192, D=256), 2 layers. Legacy HMMA is throughput-bound at ~177 TF/s
// on sm_103, so R8 cuts MMA work 3->2 passes: fp16 split activations
// (Ah+Al ~ 22 bits, exact) x single-fp16 weights. fp32 register accum.
// C = Ah*W + Al*W. Per-GEMM normwise err ~1.7e-4 (fp16 weight rounding).

#define GN 8192
#define GD 256

// ---------------- scratch (__device__ globals; no allocation allowed) ----------------
__device__ __half g_Ah[GN * GD];
__device__ __half g_Al[GN * GD];
__device__ __half g_Bh[GN * GD];
__device__ __half g_Bl[GN * GD];
__device__ __half g_W1[GD * GD];
__device__ __half g_W2[GD * GD];
__device__ float g_F[GN * GD];

// ---------------- PTX helpers (sm_80-era, compute_103-legal) ----------------
__device__ __forceinline__ uint32_t smem_u32(const void* p) {
    uint32_t a;
    asm("{ .reg .u64 t; cvta.to.shared.u64 t, %1; cvt.u32.u64 %0, t; }"
        : "=r"(a) : "l"(p));
    return a;
}

__device__ __forceinline__ void cp_async16(uint32_t s, const void* g) {
    asm volatile("cp.async.cg.shared.global [%0], [%1], 16;" :: "r"(s), "l"(g));
}
#define CP_COMMIT() asm volatile("cp.async.commit_group;" ::: "memory")
#define CP_WAIT(n)  asm volatile("cp.async.wait_group %0;" :: "n"(n) : "memory")

__device__ __forceinline__ void ldsm_x4(uint32_t* r, uint32_t addr) {
    asm volatile("ldmatrix.sync.aligned.m8n8.x4.shared.b16 {%0,%1,%2,%3}, [%4];"
                 : "=r"(r[0]), "=r"(r[1]), "=r"(r[2]), "=r"(r[3]) : "r"(addr));
}

__device__ __forceinline__ void mma16816(float* d, const uint32_t* a,
                                         const uint32_t* b) {
    asm volatile(
        "mma.sync.aligned.m16n8k16.row.col.f32.f16.f16.f32 "
        "{%0,%1,%2,%3}, {%4,%5,%6,%7}, {%8,%9}, {%0,%1,%2,%3};"
        : "+f"(d[0]), "+f"(d[1]), "+f"(d[2]), "+f"(d[3])
        : "r"(a[0]), "r"(a[1]), "r"(a[2]), "r"(a[3]), "r"(b[0]), "r"(b[1]));
}

__device__ __forceinline__ void split2h(float v, __half& h, __half& l) {
    h = __float2half_rn(v);
    l = __float2half_rn(v - __half2float(h));
}

// ---------------- GEMM tiling ----------------
#define BM 64
#define BN 64
#define BK 32
#define NCHUNK (GD / BK)              // 8
#define LDT 40                        // padded row stride (fp16 elems)
#define TILE_T (64 * LDT * 2)         // 5120 B per 64x32 fp16 tile
#define OFF_AH 0
#define OFF_AL TILE_T
#define OFF_W  (2 * TILE_T)
#define STAGE_B (3 * TILE_T)          // 15360
#define NSTAGE 3
#define SMEM_TOTAL (NSTAGE * STAGE_B) // 46080

// fragment bundle for one k16 slice (per warp)
struct Frag {
    uint32_t ah[2][4], al[2][4];   // two m16 tiles, hi/lo activations
    uint32_t w[2][4];              // two n16 tiles, fp16 weights
};

// C[8192,256] = A @ W^T + bias; A as fp16 (hi,lo), W single fp16.
// grid (128, 4); 128 thr = 4 warps in 2(m) x 2(n); warp tile 32x32.
template <bool RELU, bool WSPLIT, bool WF32, bool F32_COND>
__global__ void __launch_bounds__(128, 3)
gemm_mma(const __half* __restrict__ Ah, const __half* __restrict__ Al,
         const __half* __restrict__ W,
         const float* __restrict__ bias, const float* __restrict__ eps,
         __half* __restrict__ Oh, __half* __restrict__ Ol,
         float* __restrict__ Of) {
    extern __shared__ __align__(16) char smem[];
    const uint32_t sb = smem_u32(smem);
    const int tid = threadIdx.x;
    const int wid = tid >> 5;
    const int lane = tid & 31;
    const int warp_m = wid & 1;
    const int warp_n = wid >> 1;
    const int bm = blockIdx.x * BM;
    const int bn = blockIdx.y * BN;

    float acc[2][4][4];
#pragma unroll
    for (int i = 0; i < 2; i++)
#pragma unroll
        for (int j = 0; j < 4; j++)
#pragma unroll
            for (int k = 0; k < 4; k++) acc[i][j][k] = 0.0f;

    const uint32_t a_off_base =
        (uint32_t)((warp_m * 32 + (lane & 15)) * LDT + (lane >> 4) * 8) * 2;
    const int mmat = lane >> 3;
    const uint32_t w_off_base =
        (uint32_t)((warp_n * 32 + (lane & 7) + ((mmat >> 1) & 1) * 8) * LDT +
                   (mmat & 1) * 8) * 2;

    auto ld_frag = [&](Frag& f, uint32_t stage_base, int k16) {
        const uint32_t kadd = (uint32_t)(k16 * 16) * 2;
#pragma unroll
        for (int mi = 0; mi < 2; mi++) {
            const uint32_t off = a_off_base + kadd + (uint32_t)(mi * 16 * LDT) * 2;
            ldsm_x4(f.ah[mi], stage_base + OFF_AH + off);
            ldsm_x4(f.al[mi], stage_base + OFF_AL + off);
        }
#pragma unroll
        for (int ni = 0; ni < 2; ni++) {
            const uint32_t off = w_off_base + kadd + (uint32_t)(ni * 16 * LDT) * 2;
            ldsm_x4(f.w[ni], stage_base + OFF_W + off);
        }
    };

    // pass-major MMA: 2 passes (hi, lo), same-acc ops 8 apart
    auto do_mma = [&](const Frag& f) {
#pragma unroll
        for (int mi = 0; mi < 2; mi++)
#pragma unroll
            for (int n8 = 0; n8 < 4; n8++)
                mma16816(acc[mi][n8], f.ah[mi], &f.w[n8 >> 1][(n8 & 1) * 2]);
#pragma unroll
        for (int mi = 0; mi < 2; mi++)
#pragma unroll
            for (int n8 = 0; n8 < 4; n8++)
                mma16816(acc[mi][n8], f.al[mi], &f.w[n8 >> 1][(n8 & 1) * 2]);
    };

    auto load_stage = [&](int s, int kc) {
        const uint32_t base = sb + s * STAGE_B;
        const int k0 = kc * BK;
#pragma unroll
        for (int it = 0; it < 2; it++) {
            const int j = tid + it * 128;      // 0..255
            const int row = j >> 2;            // 0..63
            const int q = j & 3;
            const uint32_t soff = (uint32_t)(row * LDT + q * 8) * 2;
            const size_t ga = (size_t)(bm + row) * GD + k0 + q * 8;
            const size_t gw = (size_t)(bn + row) * GD + k0 + q * 8;
            cp_async16(base + OFF_AH + soff, Ah + ga);
            cp_async16(base + OFF_AL + soff, Al + ga);
            cp_async16(base + OFF_W + soff, W + gw);
        }
    };

    // ---- prologue: 2 stages in flight, fragments for (0, k16=0) resident
    load_stage(0, 0);
    CP_COMMIT();
    load_stage(1, 1);
    CP_COMMIT();
    CP_WAIT(1);
    __syncthreads();

    Frag cur, nxt;
    ld_frag(cur, sb + 0 * STAGE_B, 0);

    int stage = 0;
    for (int kc = 0; kc < NCHUNK; kc++) {
        const uint32_t base = sb + stage * STAGE_B;
        ld_frag(nxt, base, 1);
        do_mma(cur);

        if (kc < NCHUNK - 2) {
            load_stage((stage + 2) % NSTAGE, kc + 2);
            CP_COMMIT();
        }
        if (kc < NCHUNK - 1) {
            if (kc < NCHUNK - 2) { CP_WAIT(1); } else { CP_WAIT(0); }
            __syncthreads();
        }

        do_mma(nxt);
        if (kc < NCHUNK - 1) {
            stage = (stage + 1) % NSTAGE;
            ld_frag(cur, sb + stage * STAGE_B, 0);
        }
    }

    // ---- epilogue
    const bool do_f32 = WF32 && (!F32_COND || __ldg(eps) != 0.0f);
    const int r = lane >> 2;
    const int c2 = (lane & 3) * 2;
#pragma unroll
    for (int mi = 0; mi < 2; mi++) {
#pragma unroll
        for (int half = 0; half < 2; half++) {
            const int m = bm + warp_m * 32 + mi * 16 + r + half * 8;
#pragma unroll
            for (int n8 = 0; n8 < 4; n8++) {
                const int n = bn + warp_n * 32 + n8 * 8 + c2;
                float v0 = acc[mi][n8][half * 2 + 0] + __ldg(bias + n);
                float v1 = acc[mi][n8][half * 2 + 1] + __ldg(bias + n + 1);
                if (RELU) { v0 = fmaxf(v0, 0.0f); v1 = fmaxf(v1, 0.0f); }
                if (WF32) {
                    if (do_f32)
                        *(float2*)(Of + (size_t)m * GD + n) = make_float2(v0, v1);
                }
                if (WSPLIT) {
                    __half h0, l0, h1, l1;
                    split2h(v0, h0, l0);
                    split2h(v1, h1, l1);
                    __half2 hp, lp;
                    hp.x = h0; hp.y = h1;
                    lp.x = l0; lp.y = l1;
                    *(__half2*)(Oh + (size_t)m * GD + n) = hp;
                    *(__half2*)(Ol + (size_t)m * GD + n) = lp;
                }
            }
        }
    }
}

// ---------------------------------------------------------------------------
// Weight convert: W1,W2 fp32 -> fp16
// ---------------------------------------------------------------------------
__global__ void __launch_bounds__(256) wconv_kernel(
    const float* __restrict__ W1, const float* __restrict__ W2,
    __half* __restrict__ W1h, __half* __restrict__ W2h) {
    const int i = blockIdx.x * 256 + threadIdx.x;   // grid 256 -> 65536
    W1h[i] = __float2half_rn(W1[i]);
    W2h[i] = __float2half_rn(W2[i]);
}

// ---------------------------------------------------------------------------
// Input aggregation + split:  y = x + eps*(adj@x); write fp16 split(y).
// eps==0 fast path: y = x (no adj read).
// ---------------------------------------------------------------------------
__global__ void __launch_bounds__(256) split_agg_kernel(
    const float* __restrict__ x, const float* __restrict__ adj,
    const float* __restrict__ eps,
    __half* __restrict__ oh, __half* __restrict__ ol) {
    const float e = eps[0];
    const int i0 = blockIdx.x * blockDim.x + threadIdx.x;
    const int stride = gridDim.x * blockDim.x;
    if (e == 0.0f) {
        const float4* x4 = (const float4*)x;
        for (int i = i0; i < GN * GD / 8; i += stride) {
            float4 a = x4[2 * i];
            float4 b = x4[2 * i + 1];
            __half h[8], l[8];
            split2h(a.x, h[0], l[0]); split2h(a.y, h[1], l[1]);
            split2h(a.z, h[2], l[2]); split2h(a.w, h[3], l[3]);
            split2h(b.x, h[4], l[4]); split2h(b.y, h[5], l[5]);
            split2h(b.z, h[6], l[6]); split2h(b.w, h[7], l[7]);
            *(uint4*)(oh + (size_t)i * 8) = *(uint4*)h;
            *(uint4*)(ol + (size_t)i * 8) = *(uint4*)l;
        }
    } else {
        for (int i = i0; i < GN * GD; i += stride) {
            const int row = i >> 8, col = i & 255;
            float s = 0.0f;
            const float* arow = adj + (size_t)row * GN;
            for (int k = 0; k < GN; k++) s += arow[k] * x[(size_t)k * GD + col];
            __half h, l;
            split2h(x[i] + e * s, h, l);
            oh[i] = h; ol[i] = l;
        }
    }
}

// Between-layer fixup: if eps != 0, recompute split(x + eps*adj@x) from fp32.
__global__ void __launch_bounds__(256) agg_fix_kernel(
    const float* __restrict__ xin, const float* __restrict__ adj,
    const float* __restrict__ eps,
    __half* __restrict__ oh, __half* __restrict__ ol) {
    const float e = eps[0];
    if (e == 0.0f) return;
    const int i0 = blockIdx.x * blockDim.x + threadIdx.x;
    const int stride = gridDim.x * blockDim.x;
    for (int i = i0; i < GN * GD; i += stride) {
        const int row = i >> 8, col = i & 255;
        float s = 0.0f;
        const float* arow = adj + (size_t)row * GN;
        for (int k = 0; k < GN; k++) s += arow[k] * xin[(size_t)k * GD + col];
        __half h, l;
        split2h(xin[i] + e * s, h, l);
        oh[i] = h; ol[i] = l;
    }
}

// ---------------------------------------------------------------------------
// kernel_launch
// ---------------------------------------------------------------------------
extern "C" void kernel_launch(void* const* d_in, const int* in_sizes, int n_in,
                              void* d_out, int out_size) {
    const float* x   = (const float*)d_in[0];
    const float* adj = (const float*)d_in[1];
    const float* W1  = (const float*)d_in[2];
    const float* b1  = (const float*)d_in[3];
    const float* W2  = (const float*)d_in[4];
    const float* b2  = (const float*)d_in[5];
    const float* eps = (const float*)d_in[6];
    float* out = (float*)d_out;

    __half *Ah, *Al, *Bh, *Bl, *W1h, *W2h;
    float* F;
    cudaGetSymbolAddress((void**)&Ah, g_Ah);
    cudaGetSymbolAddress((void**)&Al, g_Al);
    cudaGetSymbolAddress((void**)&Bh, g_Bh);
    cudaGetSymbolAddress((void**)&Bl, g_Bl);
    cudaGetSymbolAddress((void**)&W1h, g_W1);
    cudaGetSymbolAddress((void**)&W2h, g_W2);
    cudaGetSymbolAddress((void**)&F, g_F);

    cudaFuncSetAttribute(gemm_mma<true, true, false, false>,
                         cudaFuncAttributeMaxDynamicSharedMemorySize, SMEM_TOTAL);
    cudaFuncSetAttribute(gemm_mma<false, true, true, true>,
                         cudaFuncAttributeMaxDynamicSharedMemorySize, SMEM_TOTAL);
    cudaFuncSetAttribute(gemm_mma<false, false, true, false>,
                         cudaFuncAttributeMaxDynamicSharedMemorySize, SMEM_TOTAL);

    const dim3 ggrid(GN / BM, GD / BN);   // (128, 4) = 512 CTAs

    // prep
    wconv_kernel<<<256, 256>>>(W1, W2, W1h, W2h);
    split_agg_kernel<<<1184, 256>>>(x, adj, eps, Ah, Al);

    // layer 1
    gemm_mma<true, true, false, false><<<ggrid, 128, SMEM_TOTAL>>>(
        Ah, Al, W1h, b1, eps, Bh, Bl, nullptr);
    gemm_mma<false, true, true, true><<<ggrid, 128, SMEM_TOTAL>>>(
        Bh, Bl, W2h, b2, eps, Ah, Al, F);

    // layer 2
    agg_fix_kernel<<<512, 256>>>(F, adj, eps, Ah, Al);
    gemm_mma<true, true, false, false><<<ggrid, 128, SMEM_TOTAL>>>(
        Ah, Al, W1h, b1, eps, Bh, Bl, nullptr);
    gemm_mma<false, false, true, false><<<ggrid, 128, SMEM_TOTAL>>>(
        Bh, Bl, W2h, b2, eps, nullptr, nullptr, out);
}

// round 10
// speedup vs baseline: 1.0234x; 1.0234x over previous
#include <cuda_runtime.h>
#include <cuda_fp16.h>
#include <cstdint>

// GIN (N=8192, D=256), 2 layers. Legacy HMMA is throughput-bound at ~177 TF/s
// on sm_103, so R8 cuts MMA work 3->2 passes: fp16 split activations
// (Ah+Al ~ 22 bits, exact) x single-fp16 weights. fp32 register accum.
// C = Ah*W + Al*W. Per-GEMM normwise err ~1.7e-4 (fp16 weight rounding).

#define GN 8192
#define GD 256

// ---------------- scratch (__device__ globals; no allocation allowed) ----------------
__device__ __half g_Ah[GN * GD];
__device__ __half g_Al[GN * GD];
__device__ __half g_Bh[GN * GD];
__device__ __half g_Bl[GN * GD];
__device__ __half g_W1[GD * GD];
__device__ __half g_W2[GD * GD];
__device__ float g_F[GN * GD];

// ---------------- PTX helpers (sm_80-era, compute_103-legal) ----------------
__device__ __forceinline__ uint32_t smem_u32(const void* p) {
    uint32_t a;
    asm("{ .reg .u64 t; cvta.to.shared.u64 t, %1; cvt.u32.u64 %0, t; }"
        : "=r"(a) : "l"(p));
    return a;
}

__device__ __forceinline__ void cp_async16(uint32_t s, const void* g) {
    asm volatile("cp.async.cg.shared.global [%0], [%1], 16;" :: "r"(s), "l"(g));
}
#define CP_COMMIT() asm volatile("cp.async.commit_group;" ::: "memory")
#define CP_WAIT(n)  asm volatile("cp.async.wait_group %0;" :: "n"(n) : "memory")

__device__ __forceinline__ void ldsm_x4(uint32_t* r, uint32_t addr) {
    asm volatile("ldmatrix.sync.aligned.m8n8.x4.shared.b16 {%0,%1,%2,%3}, [%4];"
                 : "=r"(r[0]), "=r"(r[1]), "=r"(r[2]), "=r"(r[3]) : "r"(addr));
}

__device__ __forceinline__ void mma16816(float* d, const uint32_t* a,
                                         const uint32_t* b) {
    asm volatile(
        "mma.sync.aligned.m16n8k16.row.col.f32.f16.f16.f32 "
        "{%0,%1,%2,%3}, {%4,%5,%6,%7}, {%8,%9}, {%0,%1,%2,%3};"
        : "+f"(d[0]), "+f"(d[1]), "+f"(d[2]), "+f"(d[3])
        : "r"(a[0]), "r"(a[1]), "r"(a[2]), "r"(a[3]), "r"(b[0]), "r"(b[1]));
}

__device__ __forceinline__ void split2h(float v, __half& h, __half& l) {
    h = __float2half_rn(v);
    l = __float2half_rn(v - __half2float(h));
}

// ---------------- GEMM tiling ----------------
#define BM 64
#define BN 64
#define BK 32
#define NCHUNK (GD / BK)              // 8
#define LDT 40                        // padded row stride (fp16 elems)
#define TILE_T (64 * LDT * 2)         // 5120 B per 64x32 fp16 tile
#define OFF_AH 0
#define OFF_AL TILE_T
#define OFF_W  (2 * TILE_T)
#define STAGE_B (3 * TILE_T)          // 15360
#define NSTAGE 3
#define SMEM_TOTAL (NSTAGE * STAGE_B) // 46080

// fragment bundle for one k16 slice (per warp)
struct Frag {
    uint32_t ah[2][4], al[2][4];   // two m16 tiles, hi/lo activations
    uint32_t w[2][4];              // two n16 tiles, fp16 weights
};

// C[8192,256] = A @ W^T + bias; A as fp16 (hi,lo), W single fp16.
// grid (128, 4); 128 thr = 4 warps in 2(m) x 2(n); warp tile 32x32.
template <bool RELU, bool WSPLIT, bool WF32, bool F32_COND>
__global__ void __launch_bounds__(128, 3)
gemm_mma(const __half* __restrict__ Ah, const __half* __restrict__ Al,
         const __half* __restrict__ W,
         const float* __restrict__ bias, const float* __restrict__ eps,
         __half* __restrict__ Oh, __half* __restrict__ Ol,
         float* __restrict__ Of) {
    extern __shared__ __align__(16) char smem[];
    const uint32_t sb = smem_u32(smem);
    const int tid = threadIdx.x;
    const int wid = tid >> 5;
    const int lane = tid & 31;
    const int warp_m = wid & 1;
    const int warp_n = wid >> 1;
    const int bm = blockIdx.x * BM;
    const int bn = blockIdx.y * BN;

    float acc[2][4][4];
#pragma unroll
    for (int i = 0; i < 2; i++)
#pragma unroll
        for (int j = 0; j < 4; j++)
#pragma unroll
            for (int k = 0; k < 4; k++) acc[i][j][k] = 0.0f;

    const uint32_t a_off_base =
        (uint32_t)((warp_m * 32 + (lane & 15)) * LDT + (lane >> 4) * 8) * 2;
    const int mmat = lane >> 3;
    const uint32_t w_off_base =
        (uint32_t)((warp_n * 32 + (lane & 7) + ((mmat >> 1) & 1) * 8) * LDT +
                   (mmat & 1) * 8) * 2;

    auto ld_frag = [&](Frag& f, uint32_t stage_base, int k16) {
        const uint32_t kadd = (uint32_t)(k16 * 16) * 2;
#pragma unroll
        for (int mi = 0; mi < 2; mi++) {
            const uint32_t off = a_off_base + kadd + (uint32_t)(mi * 16 * LDT) * 2;
            ldsm_x4(f.ah[mi], stage_base + OFF_AH + off);
            ldsm_x4(f.al[mi], stage_base + OFF_AL + off);
        }
#pragma unroll
        for (int ni = 0; ni < 2; ni++) {
            const uint32_t off = w_off_base + kadd + (uint32_t)(ni * 16 * LDT) * 2;
            ldsm_x4(f.w[ni], stage_base + OFF_W + off);
        }
    };

    // pass-major MMA: 2 passes (hi, lo), same-acc ops 8 apart
    auto do_mma = [&](const Frag& f) {
#pragma unroll
        for (int mi = 0; mi < 2; mi++)
#pragma unroll
            for (int n8 = 0; n8 < 4; n8++)
                mma16816(acc[mi][n8], f.ah[mi], &f.w[n8 >> 1][(n8 & 1) * 2]);
#pragma unroll
        for (int mi = 0; mi < 2; mi++)
#pragma unroll
            for (int n8 = 0; n8 < 4; n8++)
                mma16816(acc[mi][n8], f.al[mi], &f.w[n8 >> 1][(n8 & 1) * 2]);
    };

    auto load_stage = [&](int s, int kc) {
        const uint32_t base = sb + s * STAGE_B;
        const int k0 = kc * BK;
#pragma unroll
        for (int it = 0; it < 2; it++) {
            const int j = tid + it * 128;      // 0..255
            const int row = j >> 2;            // 0..63
            const int q = j & 3;
            const uint32_t soff = (uint32_t)(row * LDT + q * 8) * 2;
            const size_t ga = (size_t)(bm + row) * GD + k0 + q * 8;
            const size_t gw = (size_t)(bn + row) * GD + k0 + q * 8;
            cp_async16(base + OFF_AH + soff, Ah + ga);
            cp_async16(base + OFF_AL + soff, Al + ga);
            cp_async16(base + OFF_W + soff, W + gw);
        }
    };

    // ---- prologue: 2 stages in flight, fragments for (0, k16=0) resident
    load_stage(0, 0);
    CP_COMMIT();
    load_stage(1, 1);
    CP_COMMIT();
    CP_WAIT(1);
    __syncthreads();

    Frag cur, nxt;
    ld_frag(cur, sb + 0 * STAGE_B, 0);

    int stage = 0;
    for (int kc = 0; kc < NCHUNK; kc++) {
        const uint32_t base = sb + stage * STAGE_B;
        ld_frag(nxt, base, 1);
        do_mma(cur);

        if (kc < NCHUNK - 2) {
            load_stage((stage + 2) % NSTAGE, kc + 2);
            CP_COMMIT();
        }
        if (kc < NCHUNK - 1) {
            if (kc < NCHUNK - 2) { CP_WAIT(1); } else { CP_WAIT(0); }
            __syncthreads();
        }

        do_mma(nxt);
        if (kc < NCHUNK - 1) {
            stage = (stage + 1) % NSTAGE;
            ld_frag(cur, sb + stage * STAGE_B, 0);
        }
    }

    // ---- epilogue
    const bool do_f32 = WF32 && (!F32_COND || __ldg(eps) != 0.0f);
    const int r = lane >> 2;
    const int c2 = (lane & 3) * 2;
#pragma unroll
    for (int mi = 0; mi < 2; mi++) {
#pragma unroll
        for (int half = 0; half < 2; half++) {
            const int m = bm + warp_m * 32 + mi * 16 + r + half * 8;
#pragma unroll
            for (int n8 = 0; n8 < 4; n8++) {
                const int n = bn + warp_n * 32 + n8 * 8 + c2;
                float v0 = acc[mi][n8][half * 2 + 0] + __ldg(bias + n);
                float v1 = acc[mi][n8][half * 2 + 1] + __ldg(bias + n + 1);
                if (RELU) { v0 = fmaxf(v0, 0.0f); v1 = fmaxf(v1, 0.0f); }
                if (WF32) {
                    if (do_f32)
                        *(float2*)(Of + (size_t)m * GD + n) = make_float2(v0, v1);
                }
                if (WSPLIT) {
                    __half h0, l0, h1, l1;
                    split2h(v0, h0, l0);
                    split2h(v1, h1, l1);
                    __half2 hp, lp;
                    hp.x = h0; hp.y = h1;
                    lp.x = l0; lp.y = l1;
                    *(__half2*)(Oh + (size_t)m * GD + n) = hp;
                    *(__half2*)(Ol + (size_t)m * GD + n) = lp;
                }
            }
        }
    }
}

// ---------------------------------------------------------------------------
// Weight convert: W1,W2 fp32 -> fp16
// ---------------------------------------------------------------------------
__global__ void __launch_bounds__(256) wconv_kernel(
    const float* __restrict__ W1, const float* __restrict__ W2,
    __half* __restrict__ W1h, __half* __restrict__ W2h) {
    const int i = blockIdx.x * 256 + threadIdx.x;   // grid 256 -> 65536
    W1h[i] = __float2half_rn(W1[i]);
    W2h[i] = __float2half_rn(W2[i]);
}

// ---------------------------------------------------------------------------
// Input aggregation + split:  y = x + eps*(adj@x); write fp16 split(y).
// eps==0 fast path: y = x (no adj read).
// ---------------------------------------------------------------------------
__global__ void __launch_bounds__(256) split_agg_kernel(
    const float* __restrict__ x, const float* __restrict__ adj,
    const float* __restrict__ eps,
    __half* __restrict__ oh, __half* __restrict__ ol) {
    const float e = eps[0];
    const int i0 = blockIdx.x * blockDim.x + threadIdx.x;
    const int stride = gridDim.x * blockDim.x;
    if (e == 0.0f) {
        const float4* x4 = (const float4*)x;
        for (int i = i0; i < GN * GD / 8; i += stride) {
            float4 a = x4[2 * i];
            float4 b = x4[2 * i + 1];
            __half h[8], l[8];
            split2h(a.x, h[0], l[0]); split2h(a.y, h[1], l[1]);
            split2h(a.z, h[2], l[2]); split2h(a.w, h[3], l[3]);
            split2h(b.x, h[4], l[4]); split2h(b.y, h[5], l[5]);
            split2h(b.z, h[6], l[6]); split2h(b.w, h[7], l[7]);
            *(uint4*)(oh + (size_t)i * 8) = *(uint4*)h;
            *(uint4*)(ol + (size_t)i * 8) = *(uint4*)l;
        }
    } else {
        for (int i = i0; i < GN * GD; i += stride) {
            const int row = i >> 8, col = i & 255;
            float s = 0.0f;
            const float* arow = adj + (size_t)row * GN;
            for (int k = 0; k < GN; k++) s += arow[k] * x[(size_t)k * GD + col];
            __half h, l;
            split2h(x[i] + e * s, h, l);
            oh[i] = h; ol[i] = l;
        }
    }
}

// Between-layer fixup: if eps != 0, recompute split(x + eps*adj@x) from fp32.
__global__ void __launch_bounds__(256) agg_fix_kernel(
    const float* __restrict__ xin, const float* __restrict__ adj,
    const float* __restrict__ eps,
    __half* __restrict__ oh, __half* __restrict__ ol) {
    const float e = eps[0];
    if (e == 0.0f) return;
    const int i0 = blockIdx.x * blockDim.x + threadIdx.x;
    const int stride = gridDim.x * blockDim.x;
    for (int i = i0; i < GN * GD; i += stride) {
        const int row = i >> 8, col = i & 255;
        float s = 0.0f;
        const float* arow = adj + (size_t)row * GN;
        for (int k = 0; k < GN; k++) s += arow[k] * xin[(size_t)k * GD + col];
        __half h, l;
        split2h(xin[i] + e * s, h, l);
        oh[i] = h; ol[i] = l;
    }
}

// ---------------------------------------------------------------------------
// kernel_launch
// ---------------------------------------------------------------------------
extern "C" void kernel_launch(void* const* d_in, const int* in_sizes, int n_in,
                              void* d_out, int out_size) {
    const float* x   = (const float*)d_in[0];
    const float* adj = (const float*)d_in[1];
    const float* W1  = (const float*)d_in[2];
    const float* b1  = (const float*)d_in[3];
    const float* W2  = (const float*)d_in[4];
    const float* b2  = (const float*)d_in[5];
    const float* eps = (const float*)d_in[6];
    float* out = (float*)d_out;

    __half *Ah, *Al, *Bh, *Bl, *W1h, *W2h;
    float* F;
    cudaGetSymbolAddress((void**)&Ah, g_Ah);
    cudaGetSymbolAddress((void**)&Al, g_Al);
    cudaGetSymbolAddress((void**)&Bh, g_Bh);
    cudaGetSymbolAddress((void**)&Bl, g_Bl);
    cudaGetSymbolAddress((void**)&W1h, g_W1);
    cudaGetSymbolAddress((void**)&W2h, g_W2);
    cudaGetSymbolAddress((void**)&F, g_F);

    cudaFuncSetAttribute(gemm_mma<true, true, false, false>,
                         cudaFuncAttributeMaxDynamicSharedMemorySize, SMEM_TOTAL);
    cudaFuncSetAttribute(gemm_mma<false, true, true, true>,
                         cudaFuncAttributeMaxDynamicSharedMemorySize, SMEM_TOTAL);
    cudaFuncSetAttribute(gemm_mma<false, false, true, false>,
                         cudaFuncAttributeMaxDynamicSharedMemorySize, SMEM_TOTAL);

    const dim3 ggrid(GN / BM, GD / BN);   // (128, 4) = 512 CTAs

    // prep
    wconv_kernel<<<256, 256>>>(W1, W2, W1h, W2h);
    split_agg_kernel<<<1184, 256>>>(x, adj, eps, Ah, Al);

    // layer 1
    gemm_mma<true, true, false, false><<<ggrid, 128, SMEM_TOTAL>>>(
        Ah, Al, W1h, b1, eps, Bh, Bl, nullptr);
    gemm_mma<false, true, true, true><<<ggrid, 128, SMEM_TOTAL>>>(
        Bh, Bl, W2h, b2, eps, Ah, Al, F);

    // layer 2
    agg_fix_kernel<<<512, 256>>>(F, adj, eps, Ah, Al);
    gemm_mma<true, true, false, false><<<ggrid, 128, SMEM_TOTAL>>>(
        Ah, Al, W1h, b1, eps, Bh, Bl, nullptr);
    gemm_mma<false, false, true, false><<<ggrid, 128, SMEM_TOTAL>>>(
        Bh, Bl, W2h, b2, eps, nullptr, nullptr, out);
}

// round 11
// speedup vs baseline: 1.0287x; 1.0052x over previous
#include <cuda_runtime.h>
#include <cuda_fp16.h>
#include <cstdint>

// GIN (N=8192, D=256), 2 layers. Legacy HMMA is throughput-bound at ~177 TF/s
// on sm_103, so R8 cuts MMA work 3->2 passes: fp16 split activations
// (Ah+Al ~ 22 bits, exact) x single-fp16 weights. fp32 register accum.
// C = Ah*W + Al*W. Per-GEMM normwise err ~1.7e-4 (fp16 weight rounding).

#define GN 8192
#define GD 256

// ---------------- scratch (__device__ globals; no allocation allowed) ----------------
__device__ __half g_Ah[GN * GD];
__device__ __half g_Al[GN * GD];
__device__ __half g_Bh[GN * GD];
__device__ __half g_Bl[GN * GD];
__device__ __half g_W1[GD * GD];
__device__ __half g_W2[GD * GD];
__device__ float g_F[GN * GD];

// ---------------- PTX helpers (sm_80-era, compute_103-legal) ----------------
__device__ __forceinline__ uint32_t smem_u32(const void* p) {
    uint32_t a;
    asm("{ .reg .u64 t; cvta.to.shared.u64 t, %1; cvt.u32.u64 %0, t; }"
        : "=r"(a) : "l"(p));
    return a;
}

__device__ __forceinline__ void cp_async16(uint32_t s, const void* g) {
    asm volatile("cp.async.cg.shared.global [%0], [%1], 16;" :: "r"(s), "l"(g));
}
#define CP_COMMIT() asm volatile("cp.async.commit_group;" ::: "memory")
#define CP_WAIT(n)  asm volatile("cp.async.wait_group %0;" :: "n"(n) : "memory")

__device__ __forceinline__ void ldsm_x4(uint32_t* r, uint32_t addr) {
    asm volatile("ldmatrix.sync.aligned.m8n8.x4.shared.b16 {%0,%1,%2,%3}, [%4];"
                 : "=r"(r[0]), "=r"(r[1]), "=r"(r[2]), "=r"(r[3]) : "r"(addr));
}

__device__ __forceinline__ void mma16816(float* d, const uint32_t* a,
                                         const uint32_t* b) {
    asm volatile(
        "mma.sync.aligned.m16n8k16.row.col.f32.f16.f16.f32 "
        "{%0,%1,%2,%3}, {%4,%5,%6,%7}, {%8,%9}, {%0,%1,%2,%3};"
        : "+f"(d[0]), "+f"(d[1]), "+f"(d[2]), "+f"(d[3])
        : "r"(a[0]), "r"(a[1]), "r"(a[2]), "r"(a[3]), "r"(b[0]), "r"(b[1]));
}

__device__ __forceinline__ void split2h(float v, __half& h, __half& l) {
    h = __float2half_rn(v);
    l = __float2half_rn(v - __half2float(h));
}

// ---------------- GEMM tiling ----------------
#define BM 64
#define BN 64
#define BK 32
#define NCHUNK (GD / BK)              // 8
#define LDT 40                        // padded row stride (fp16 elems)
#define TILE_T (64 * LDT * 2)         // 5120 B per 64x32 fp16 tile
#define OFF_AH 0
#define OFF_AL TILE_T
#define OFF_W  (2 * TILE_T)
#define STAGE_B (3 * TILE_T)          // 15360
#define NSTAGE 3
#define SMEM_TOTAL (NSTAGE * STAGE_B) // 46080

// fragment bundle for one k16 slice (per warp)
struct Frag {
    uint32_t ah[2][4], al[2][4];   // two m16 tiles, hi/lo activations
    uint32_t w[2][4];              // two n16 tiles, fp16 weights
};

// C[8192,256] = A @ W^T + bias; A as fp16 (hi,lo), W single fp16.
// grid (128, 4); 128 thr = 4 warps in 2(m) x 2(n); warp tile 32x32.
template <bool RELU, bool WSPLIT, bool WF32, bool F32_COND>
__global__ void __launch_bounds__(128, 3)
gemm_mma(const __half* __restrict__ Ah, const __half* __restrict__ Al,
         const __half* __restrict__ W,
         const float* __restrict__ bias, const float* __restrict__ eps,
         __half* __restrict__ Oh, __half* __restrict__ Ol,
         float* __restrict__ Of) {
    extern __shared__ __align__(16) char smem[];
    const uint32_t sb = smem_u32(smem);
    const int tid = threadIdx.x;
    const int wid = tid >> 5;
    const int lane = tid & 31;
    const int warp_m = wid & 1;
    const int warp_n = wid >> 1;
    const int bm = blockIdx.x * BM;
    const int bn = blockIdx.y * BN;

    float acc[2][4][4];
#pragma unroll
    for (int i = 0; i < 2; i++)
#pragma unroll
        for (int j = 0; j < 4; j++)
#pragma unroll
            for (int k = 0; k < 4; k++) acc[i][j][k] = 0.0f;

    const uint32_t a_off_base =
        (uint32_t)((warp_m * 32 + (lane & 15)) * LDT + (lane >> 4) * 8) * 2;
    const int mmat = lane >> 3;
    const uint32_t w_off_base =
        (uint32_t)((warp_n * 32 + (lane & 7) + ((mmat >> 1) & 1) * 8) * LDT +
                   (mmat & 1) * 8) * 2;

    auto ld_frag = [&](Frag& f, uint32_t stage_base, int k16) {
        const uint32_t kadd = (uint32_t)(k16 * 16) * 2;
#pragma unroll
        for (int mi = 0; mi < 2; mi++) {
            const uint32_t off = a_off_base + kadd + (uint32_t)(mi * 16 * LDT) * 2;
            ldsm_x4(f.ah[mi], stage_base + OFF_AH + off);
            ldsm_x4(f.al[mi], stage_base + OFF_AL + off);
        }
#pragma unroll
        for (int ni = 0; ni < 2; ni++) {
            const uint32_t off = w_off_base + kadd + (uint32_t)(ni * 16 * LDT) * 2;
            ldsm_x4(f.w[ni], stage_base + OFF_W + off);
        }
    };

    // pass-major MMA: 2 passes (hi, lo), same-acc ops 8 apart
    auto do_mma = [&](const Frag& f) {
#pragma unroll
        for (int mi = 0; mi < 2; mi++)
#pragma unroll
            for (int n8 = 0; n8 < 4; n8++)
                mma16816(acc[mi][n8], f.ah[mi], &f.w[n8 >> 1][(n8 & 1) * 2]);
#pragma unroll
        for (int mi = 0; mi < 2; mi++)
#pragma unroll
            for (int n8 = 0; n8 < 4; n8++)
                mma16816(acc[mi][n8], f.al[mi], &f.w[n8 >> 1][(n8 & 1) * 2]);
    };

    auto load_stage = [&](int s, int kc) {
        const uint32_t base = sb + s * STAGE_B;
        const int k0 = kc * BK;
#pragma unroll
        for (int it = 0; it < 2; it++) {
            const int j = tid + it * 128;      // 0..255
            const int row = j >> 2;            // 0..63
            const int q = j & 3;
            const uint32_t soff = (uint32_t)(row * LDT + q * 8) * 2;
            const size_t ga = (size_t)(bm + row) * GD + k0 + q * 8;
            const size_t gw = (size_t)(bn + row) * GD + k0 + q * 8;
            cp_async16(base + OFF_AH + soff, Ah + ga);
            cp_async16(base + OFF_AL + soff, Al + ga);
            cp_async16(base + OFF_W + soff, W + gw);
        }
    };

    // ---- prologue: 2 stages in flight, fragments for (0, k16=0) resident
    load_stage(0, 0);
    CP_COMMIT();
    load_stage(1, 1);
    CP_COMMIT();
    CP_WAIT(1);
    __syncthreads();

    Frag cur, nxt;
    ld_frag(cur, sb + 0 * STAGE_B, 0);

    int stage = 0;
    for (int kc = 0; kc < NCHUNK; kc++) {
        const uint32_t base = sb + stage * STAGE_B;
        ld_frag(nxt, base, 1);
        do_mma(cur);

        if (kc < NCHUNK - 2) {
            load_stage((stage + 2) % NSTAGE, kc + 2);
            CP_COMMIT();
        }
        if (kc < NCHUNK - 1) {
            if (kc < NCHUNK - 2) { CP_WAIT(1); } else { CP_WAIT(0); }
            __syncthreads();
        }

        do_mma(nxt);
        if (kc < NCHUNK - 1) {
            stage = (stage + 1) % NSTAGE;
            ld_frag(cur, sb + stage * STAGE_B, 0);
        }
    }

    // ---- epilogue
    const bool do_f32 = WF32 && (!F32_COND || __ldg(eps) != 0.0f);
    const int r = lane >> 2;
    const int c2 = (lane & 3) * 2;
#pragma unroll
    for (int mi = 0; mi < 2; mi++) {
#pragma unroll
        for (int half = 0; half < 2; half++) {
            const int m = bm + warp_m * 32 + mi * 16 + r + half * 8;
#pragma unroll
            for (int n8 = 0; n8 < 4; n8++) {
                const int n = bn + warp_n * 32 + n8 * 8 + c2;
                float v0 = acc[mi][n8][half * 2 + 0] + __ldg(bias + n);
                float v1 = acc[mi][n8][half * 2 + 1] + __ldg(bias + n + 1);
                if (RELU) { v0 = fmaxf(v0, 0.0f); v1 = fmaxf(v1, 0.0f); }
                if (WF32) {
                    if (do_f32)
                        *(float2*)(Of + (size_t)m * GD + n) = make_float2(v0, v1);
                }
                if (WSPLIT) {
                    __half h0, l0, h1, l1;
                    split2h(v0, h0, l0);
                    split2h(v1, h1, l1);
                    __half2 hp, lp;
                    hp.x = h0; hp.y = h1;
                    lp.x = l0; lp.y = l1;
                    *(__half2*)(Oh + (size_t)m * GD + n) = hp;
                    *(__half2*)(Ol + (size_t)m * GD + n) = lp;
                }
            }
        }
    }
}

// ---------------------------------------------------------------------------
// Weight convert: W1,W2 fp32 -> fp16
// ---------------------------------------------------------------------------
__global__ void __launch_bounds__(256) wconv_kernel(
    const float* __restrict__ W1, const float* __restrict__ W2,
    __half* __restrict__ W1h, __half* __restrict__ W2h) {
    const int i = blockIdx.x * 256 + threadIdx.x;   // grid 256 -> 65536
    W1h[i] = __float2half_rn(W1[i]);
    W2h[i] = __float2half_rn(W2[i]);
}

// ---------------------------------------------------------------------------
// Input aggregation + split:  y = x + eps*(adj@x); write fp16 split(y).
// eps==0 fast path: y = x (no adj read).
// ---------------------------------------------------------------------------
__global__ void __launch_bounds__(256) split_agg_kernel(
    const float* __restrict__ x, const float* __restrict__ adj,
    const float* __restrict__ eps,
    __half* __restrict__ oh, __half* __restrict__ ol) {
    const float e = eps[0];
    const int i0 = blockIdx.x * blockDim.x + threadIdx.x;
    const int stride = gridDim.x * blockDim.x;
    if (e == 0.0f) {
        const float4* x4 = (const float4*)x;
        for (int i = i0; i < GN * GD / 8; i += stride) {
            float4 a = x4[2 * i];
            float4 b = x4[2 * i + 1];
            __half h[8], l[8];
            split2h(a.x, h[0], l[0]); split2h(a.y, h[1], l[1]);
            split2h(a.z, h[2], l[2]); split2h(a.w, h[3], l[3]);
            split2h(b.x, h[4], l[4]); split2h(b.y, h[5], l[5]);
            split2h(b.z, h[6], l[6]); split2h(b.w, h[7], l[7]);
            *(uint4*)(oh + (size_t)i * 8) = *(uint4*)h;
            *(uint4*)(ol + (size_t)i * 8) = *(uint4*)l;
        }
    } else {
        for (int i = i0; i < GN * GD; i += stride) {
            const int row = i >> 8, col = i & 255;
            float s = 0.0f;
            const float* arow = adj + (size_t)row * GN;
            for (int k = 0; k < GN; k++) s += arow[k] * x[(size_t)k * GD + col];
            __half h, l;
            split2h(x[i] + e * s, h, l);
            oh[i] = h; ol[i] = l;
        }
    }
}

// Between-layer fixup: if eps != 0, recompute split(x + eps*adj@x) from fp32.
__global__ void __launch_bounds__(256) agg_fix_kernel(
    const float* __restrict__ xin, const float* __restrict__ adj,
    const float* __restrict__ eps,
    __half* __restrict__ oh, __half* __restrict__ ol) {
    const float e = eps[0];
    if (e == 0.0f) return;
    const int i0 = blockIdx.x * blockDim.x + threadIdx.x;
    const int stride = gridDim.x * blockDim.x;
    for (int i = i0; i < GN * GD; i += stride) {
        const int row = i >> 8, col = i & 255;
        float s = 0.0f;
        const float* arow = adj + (size_t)row * GN;
        for (int k = 0; k < GN; k++) s += arow[k] * xin[(size_t)k * GD + col];
        __half h, l;
        split2h(xin[i] + e * s, h, l);
        oh[i] = h; ol[i] = l;
    }
}

// ---------------------------------------------------------------------------
// kernel_launch
// ---------------------------------------------------------------------------
extern "C" void kernel_launch(void* const* d_in, const int* in_sizes, int n_in,
                              void* d_out, int out_size) {
    const float* x   = (const float*)d_in[0];
    const float* adj = (const float*)d_in[1];
    const float* W1  = (const float*)d_in[2];
    const float* b1  = (const float*)d_in[3];
    const float* W2  = (const float*)d_in[4];
    const float* b2  = (const float*)d_in[5];
    const float* eps = (const float*)d_in[6];
    float* out = (float*)d_out;

    __half *Ah, *Al, *Bh, *Bl, *W1h, *W2h;
    float* F;
    cudaGetSymbolAddress((void**)&Ah, g_Ah);
    cudaGetSymbolAddress((void**)&Al, g_Al);
    cudaGetSymbolAddress((void**)&Bh, g_Bh);
    cudaGetSymbolAddress((void**)&Bl, g_Bl);
    cudaGetSymbolAddress((void**)&W1h, g_W1);
    cudaGetSymbolAddress((void**)&W2h, g_W2);
    cudaGetSymbolAddress((void**)&F, g_F);

    cudaFuncSetAttribute(gemm_mma<true, true, false, false>,
                         cudaFuncAttributeMaxDynamicSharedMemorySize, SMEM_TOTAL);
    cudaFuncSetAttribute(gemm_mma<false, true, true, true>,
                         cudaFuncAttributeMaxDynamicSharedMemorySize, SMEM_TOTAL);
    cudaFuncSetAttribute(gemm_mma<false, false, true, false>,
                         cudaFuncAttributeMaxDynamicSharedMemorySize, SMEM_TOTAL);

    const dim3 ggrid(GN / BM, GD / BN);   // (128, 4) = 512 CTAs

    // prep
    wconv_kernel<<<256, 256>>>(W1, W2, W1h, W2h);
    split_agg_kernel<<<1184, 256>>>(x, adj, eps, Ah, Al);

    // layer 1
    gemm_mma<true, true, false, false><<<ggrid, 128, SMEM_TOTAL>>>(
        Ah, Al, W1h, b1, eps, Bh, Bl, nullptr);
    gemm_mma<false, true, true, true><<<ggrid, 128, SMEM_TOTAL>>>(
        Bh, Bl, W2h, b2, eps, Ah, Al, F);

    // layer 2
    agg_fix_kernel<<<512, 256>>>(F, adj, eps, Ah, Al);
    gemm_mma<true, true, false, false><<<ggrid, 128, SMEM_TOTAL>>>(
        Ah, Al, W1h, b1, eps, Bh, Bl, nullptr);
    gemm_mma<false, false, true, false><<<ggrid, 128, SMEM_TOTAL>>>(
        Bh, Bl, W2h, b2, eps, nullptr, nullptr, out);
}